// round 13
// baseline (speedup 1.0000x reference)
#include <cuda_runtime.h>
#include <cstdint>

// YOLOv1 loss: pred [4096,14,14,30] fp32, target same, output scalar fp32.
// R13 = R12 (double-buffered per-thread cp.async, 7 blocks/SM x 4 warps) with
// GRID_N=896: 896 | 12544 -> exactly 14 tiles per block, zero straggler tail,
// single wave (896 < 1036 resident capacity). Device is at its ~5.5TB/s
// streaming ceiling; this removes the last structural defect (imbalance).

#define NBATCH     4096
#define NCH        30
#define NCELLS     (NBATCH * 14 * 14)          // 802816
#define TILE_C     64
#define NTILES     (NCELLS / TILE_C)           // 12544 exact
#define BLOCK      128
#define TILE_F4    ((TILE_C * NCH) / 4)        // 480 float4 per array per tile
#define CP_TOTAL   (2 * TILE_F4)               // 960 copies per tile
#define CP_ITERS   ((CP_TOTAL + BLOCK - 1) / BLOCK)  // 8 (last partial)
#define STAGE_F    (TILE_C * NCH)              // 1920 floats per array stage
#define GRID_N     896                         // 12544 / 896 = 14 tiles/block
#define NPB        (NTILES / GRID_N)           // 14, uniform

__device__ float        g_acc;     // zero-init at load; reset by last block
__device__ unsigned int g_count;

__device__ __forceinline__ void cp_async16(uint32_t smem_dst, const void* gsrc) {
    asm volatile("cp.async.cg.shared.global [%0], [%1], 16;\n"
                 :: "r"(smem_dst), "l"(gsrc));
}

__global__ __launch_bounds__(BLOCK)
void yolo_loss_kernel(const float4* __restrict__ pred4,
                      const float4* __restrict__ tgt4,
                      float* __restrict__ out)
{
    __shared__ float sp[2][STAGE_F];   // 15360 B
    __shared__ float st[2][STAGE_F];   // 15360 B
    __shared__ float wsum[BLOCK / 32];

    const uint32_t sp_base = (uint32_t)__cvta_generic_to_shared(&sp[0][0]);
    const uint32_t st_base = (uint32_t)__cvta_generic_to_shared(&st[0][0]);

    // issue tile i into stage i%2, one commit group per tile
    auto issue = [&](int i) {
        const int base4 = (blockIdx.x + i * GRID_N) * TILE_F4;
        const uint32_t soff = (uint32_t)(i & 1) * (STAGE_F * 4u);
        #pragma unroll
        for (int k = 0; k < CP_ITERS; k++) {
            const int j = threadIdx.x + k * BLOCK;
            if (j < TILE_F4) {
                cp_async16(sp_base + soff + (uint32_t)j * 16u, pred4 + base4 + j);
            } else if (j < CP_TOTAL) {
                const int m = j - TILE_F4;
                cp_async16(st_base + soff + (uint32_t)m * 16u, tgt4 + base4 + m);
            }
        }
        asm volatile("cp.async.commit_group;\n" ::: "memory");
    };

    issue(0);

    const float invS = 1.0f / 14.0f;
    float acc = 0.0f;

    #pragma unroll 1
    for (int i = 0; i < NPB; i++) {
        if (i + 1 < NPB) {
            issue(i + 1);   // stage (i+1)&1 was freed at end of i-1
            asm volatile("cp.async.wait_group 1;\n" ::: "memory");
        } else {
            asm volatile("cp.async.wait_group 0;\n" ::: "memory");
        }
        __syncthreads();   // all threads' copies for tile i visible

        if (threadIdx.x < TILE_C) {
            const float* p = &sp[i & 1][0] + threadIdx.x * NCH;
            const float* t = &st[i & 1][0] + threadIdx.x * NCH;

            // target box 0 (boxes are tiled identical in target)
            const float t0x = t[0], t0y = t[1], t0w = t[2], t0h = t[3];
            const float tobj = t[4];
            const float of = (tobj > 0.0f) ? 1.0f : 0.0f;

            const float tcx = t0x * invS, tcy = t0y * invS;
            const float thw = 0.5f * t0w, thh = 0.5f * t0h;
            const float tx0 = tcx - thw, tx1 = tcx + thw;
            const float ty0 = tcy - thh, ty1 = tcy + thh;
            const float area_t = t0w * t0h;

            float iou[2], px[2], py[2], pw[2], ph[2], pc[2];
            #pragma unroll
            for (int b = 0; b < 2; b++) {
                px[b] = p[5*b + 0]; py[b] = p[5*b + 1];
                pw[b] = p[5*b + 2]; ph[b] = p[5*b + 3];
                pc[b] = p[5*b + 4];
                const float pcx = px[b] * invS, pcy = py[b] * invS;
                const float phw = 0.5f * pw[b], phh = 0.5f * ph[b];
                const float px0 = pcx - phw, px1 = pcx + phw;
                const float py0 = pcy - phh, py1 = pcy + phh;
                const float ltx = fmaxf(px0, tx0), lty = fmaxf(py0, ty0);
                const float rbx = fminf(px1, tx1), rby = fminf(py1, ty1);
                const float wi = fmaxf(rbx - ltx, 0.0f);
                const float hi = fmaxf(rby - lty, 0.0f);
                const float inter = wi * hi;
                const float area_p = pw[b] * ph[b];
                iou[b] = inter / (area_p + area_t - inter);
            }

            // argmax over 2 boxes; ties -> box 0 (matches jnp.argmax)
            const int b = (iou[1] > iou[0]) ? 1 : 0;
            const float max_iou = fmaxf(iou[0], iou[1]);

            const float dx = px[b] - t0x, dy = py[b] - t0y;
            const float lxy = dx*dx + dy*dy;
            const float dw = sqrtf(pw[b]) - sqrtf(t0w);
            const float dh = sqrtf(ph[b]) - sqrtf(t0h);
            const float lwh = dw*dw + dh*dh;
            const float dob = pc[b] - max_iou;
            const float lobj = dob * dob;
            const float lno = pc[0]*pc[0] + pc[1]*pc[1]; // tgt conf=0 when no obj

            float lcls = 0.0f;
            #pragma unroll
            for (int c = 0; c < 20; c++) {
                const float d = p[10 + c] - t[10 + c];
                lcls += d * d;
            }

            acc += of * (5.0f * (lxy + lwh) + lobj + lcls)
                 + (1.0f - of) * (0.5f * lno);
        }
        __syncthreads();   // readers done before this stage is re-targeted
    }

    acc *= (1.0f / (float)NBATCH);

    // warp reduce, then block partial
    #pragma unroll
    for (int o = 16; o > 0; o >>= 1)
        acc += __shfl_down_sync(0xffffffffu, acc, o);
    if ((threadIdx.x & 31) == 0) wsum[threadIdx.x >> 5] = acc;
    __syncthreads();

    if (threadIdx.x == 0) {
        float ssum = 0.0f;
        #pragma unroll
        for (int w = 0; w < BLOCK / 32; w++) ssum += wsum[w];
        atomicAdd(&g_acc, ssum);
        __threadfence();
        const unsigned int done = atomicAdd(&g_count, 1u);
        if (done == GRID_N - 1) {
            // last block: publish result and reset globals for next replay
            const float total = atomicAdd(&g_acc, 0.0f);
            out[0] = total;
            atomicExch(&g_acc, 0.0f);
            atomicExch(&g_count, 0u);
        }
    }
}

extern "C" void kernel_launch(void* const* d_in, const int* in_sizes, int n_in,
                              void* d_out, int out_size)
{
    const float4* pred4 = (const float4*)d_in[0];
    const float4* tgt4  = (const float4*)d_in[1];
    float* out = (float*)d_out;

    yolo_loss_kernel<<<GRID_N, BLOCK>>>(pred4, tgt4, out);
}

// round 14
// speedup vs baseline: 1.0463x; 1.0463x over previous
#include <cuda_runtime.h>
#include <cstdint>

// YOLOv1 loss: pred [4096,14,14,30] fp32, target same, output scalar fp32.
// R14: 3-stage per-thread cp.async ring with ONE __syncthreads per tile.
// Safety: issue(i+2) targets stage (i-1)%3, whose last readers (compute i-1)
// are all past the post-wait sync of iteration i. 46080B static smem ->
// 4 blocks/SM x 4 warps. Fused last-block finalization.

#define NBATCH     4096
#define NCH        30
#define NCELLS     (NBATCH * 14 * 14)          // 802816
#define TILE_C     64
#define NTILES     (NCELLS / TILE_C)           // 12544 exact
#define BLOCK      128
#define TILE_F4    ((TILE_C * NCH) / 4)        // 480 float4 per array per tile
#define CP_TOTAL   (2 * TILE_F4)               // 960 copies per tile
#define CP_ITERS   ((CP_TOTAL + BLOCK - 1) / BLOCK)  // 8 (last partial)
#define STAGE_F    (TILE_C * NCH)              // 1920 floats per array stage
#define NSTAGE     3
#define GRID_N     592                         // 4 blocks/SM * 148 SMs

__device__ float        g_acc;     // zero-init at load; reset by last block
__device__ unsigned int g_count;

__device__ __forceinline__ void cp_async16(uint32_t smem_dst, const void* gsrc) {
    asm volatile("cp.async.cg.shared.global [%0], [%1], 16;\n"
                 :: "r"(smem_dst), "l"(gsrc));
}

__global__ __launch_bounds__(BLOCK)
void yolo_loss_kernel(const float4* __restrict__ pred4,
                      const float4* __restrict__ tgt4,
                      float* __restrict__ out)
{
    __shared__ float sp[NSTAGE][STAGE_F];   // 23040 B
    __shared__ float st[NSTAGE][STAGE_F];   // 23040 B
    __shared__ float wsum[BLOCK / 32];

    const uint32_t sp_base = (uint32_t)__cvta_generic_to_shared(&sp[0][0]);
    const uint32_t st_base = (uint32_t)__cvta_generic_to_shared(&st[0][0]);

    // this block's tiles: blockIdx.x, +GRID_N, ... (21 or 22)
    const int n = (NTILES - blockIdx.x + GRID_N - 1) / GRID_N;

    // issue tile i into stage i%NSTAGE, one commit group per tile
    auto issue = [&](int i) {
        const int base4 = (blockIdx.x + i * GRID_N) * TILE_F4;
        const uint32_t soff = (uint32_t)(i % NSTAGE) * (STAGE_F * 4u);
        #pragma unroll
        for (int k = 0; k < CP_ITERS; k++) {
            const int j = threadIdx.x + k * BLOCK;
            if (j < TILE_F4) {
                cp_async16(sp_base + soff + (uint32_t)j * 16u, pred4 + base4 + j);
            } else if (j < CP_TOTAL) {
                const int m = j - TILE_F4;
                cp_async16(st_base + soff + (uint32_t)m * 16u, tgt4 + base4 + m);
            }
        }
        asm volatile("cp.async.commit_group;\n" ::: "memory");
    };

    issue(0);   // n >= 21 always
    issue(1);

    const float invS = 1.0f / 14.0f;
    float acc = 0.0f;

    #pragma unroll 1
    for (int i = 0; i < n; i++) {
        // tile i done when at most 1 newer group (tile i+1) is pending
        if (i + 1 < n)
            asm volatile("cp.async.wait_group 1;\n" ::: "memory");
        else
            asm volatile("cp.async.wait_group 0;\n" ::: "memory");
        __syncthreads();   // single barrier: copies for tile i visible to all,
                           // AND all warps finished compute(i-1) -> stage
                           // (i+2)%3 == (i-1)%3 is free for reuse.

        if (i + 2 < n) issue(i + 2);

        const int s = i % NSTAGE;
        if (threadIdx.x < TILE_C) {
            const float* p = &sp[s][0] + threadIdx.x * NCH;
            const float* t = &st[s][0] + threadIdx.x * NCH;

            // target box 0 (boxes are tiled identical in target)
            const float t0x = t[0], t0y = t[1], t0w = t[2], t0h = t[3];
            const float tobj = t[4];
            const float of = (tobj > 0.0f) ? 1.0f : 0.0f;

            const float tcx = t0x * invS, tcy = t0y * invS;
            const float thw = 0.5f * t0w, thh = 0.5f * t0h;
            const float tx0 = tcx - thw, tx1 = tcx + thw;
            const float ty0 = tcy - thh, ty1 = tcy + thh;
            const float area_t = t0w * t0h;

            float iou[2], px[2], py[2], pw[2], ph[2], pc[2];
            #pragma unroll
            for (int b = 0; b < 2; b++) {
                px[b] = p[5*b + 0]; py[b] = p[5*b + 1];
                pw[b] = p[5*b + 2]; ph[b] = p[5*b + 3];
                pc[b] = p[5*b + 4];
                const float pcx = px[b] * invS, pcy = py[b] * invS;
                const float phw = 0.5f * pw[b], phh = 0.5f * ph[b];
                const float px0 = pcx - phw, px1 = pcx + phw;
                const float py0 = pcy - phh, py1 = pcy + phh;
                const float ltx = fmaxf(px0, tx0), lty = fmaxf(py0, ty0);
                const float rbx = fminf(px1, tx1), rby = fminf(py1, ty1);
                const float wi = fmaxf(rbx - ltx, 0.0f);
                const float hi = fmaxf(rby - lty, 0.0f);
                const float inter = wi * hi;
                const float area_p = pw[b] * ph[b];
                iou[b] = inter / (area_p + area_t - inter);
            }

            // argmax over 2 boxes; ties -> box 0 (matches jnp.argmax)
            const int b = (iou[1] > iou[0]) ? 1 : 0;
            const float max_iou = fmaxf(iou[0], iou[1]);

            const float dx = px[b] - t0x, dy = py[b] - t0y;
            const float lxy = dx*dx + dy*dy;
            const float dw = sqrtf(pw[b]) - sqrtf(t0w);
            const float dh = sqrtf(ph[b]) - sqrtf(t0h);
            const float lwh = dw*dw + dh*dh;
            const float dob = pc[b] - max_iou;
            const float lobj = dob * dob;
            const float lno = pc[0]*pc[0] + pc[1]*pc[1]; // tgt conf=0 when no obj

            float lcls = 0.0f;
            #pragma unroll
            for (int c = 0; c < 20; c++) {
                const float d = p[10 + c] - t[10 + c];
                lcls += d * d;
            }

            acc += of * (5.0f * (lxy + lwh) + lobj + lcls)
                 + (1.0f - of) * (0.5f * lno);
        }
    }

    acc *= (1.0f / (float)NBATCH);

    // warp reduce, then block partial
    #pragma unroll
    for (int o = 16; o > 0; o >>= 1)
        acc += __shfl_down_sync(0xffffffffu, acc, o);
    if ((threadIdx.x & 31) == 0) wsum[threadIdx.x >> 5] = acc;
    __syncthreads();

    if (threadIdx.x == 0) {
        float ssum = 0.0f;
        #pragma unroll
        for (int w = 0; w < BLOCK / 32; w++) ssum += wsum[w];
        atomicAdd(&g_acc, ssum);
        __threadfence();
        const unsigned int done = atomicAdd(&g_count, 1u);
        if (done == GRID_N - 1) {
            // last block: publish result and reset globals for next replay
            const float total = atomicAdd(&g_acc, 0.0f);
            out[0] = total;
            atomicExch(&g_acc, 0.0f);
            atomicExch(&g_count, 0u);
        }
    }
}

extern "C" void kernel_launch(void* const* d_in, const int* in_sizes, int n_in,
                              void* d_out, int out_size)
{
    const float4* pred4 = (const float4*)d_in[0];
    const float4* tgt4  = (const float4*)d_in[1];
    float* out = (float*)d_out;

    yolo_loss_kernel<<<GRID_N, BLOCK>>>(pred4, tgt4, out);
}